// round 8
// baseline (speedup 1.0000x reference)
#include <cuda_runtime.h>
#include <cuda_bf16.h>
#include <mma.h>
#include <cstdint>

using namespace nvcuda;

#define NT 512
#define NWARP 16
#define T_ITER 8
#define TSIZE (1u << 19)
#define TMASK (TSIZE - 1u)

// floor(16 * 1.3819^l)
__constant__ unsigned c_res[16] = {16u, 22u, 30u, 42u, 58u, 80u, 111u, 153u,
                                   212u, 294u, 406u, 561u, 775u, 1072u, 1481u, 2047u};

// wr3 (64x4 padded) in constant memory for the final scalar layer
__constant__ float c_w3[256];
__device__ float g_w3[256];

// ---- smem layout (bytes) ----
// weight matrices: bf16, row-major [k][n], hi and lo parts
#define SM_WS1H 0
#define SM_WS1L 4608
#define SM_WS2H 9216
#define SM_WS2L 14336
#define SM_WR1H 19456
#define SM_WR1L 24064
#define SM_WR2H 28672
#define SM_WR2L 37888
#define SM_WARP0 47104
// per-warp: A_hi (32x72 bf16 = 4608) + A_lo (4608) + C scratch (16x32 fp32 = 2048)
#define WARP_BYTES 11264
#define SMEM_BYTES (SM_WARP0 + NWARP * WARP_BYTES)   // 227,328 < 232,448 cap

#define A_STRIDE 72

__device__ __forceinline__ float sigmoidf_(float x) { return 1.0f / (1.0f + __expf(-x)); }

// Split-precision dense layer with relu epilogue, warp-local.
// Ah/Al: warp's activation hi/lo planes (32 rows x A_STRIDE bf16).
// D = Ah*Bh + Ah*Bl + Al*Bh, fp32 accum; relu'd result re-split hi/lo into Ah/Al.
// Strict row locality: strip s reads/writes rows [s*16, s*16+16) only.
template <int KT, int NTT>
__device__ __forceinline__ void dense_wmma_relu(__nv_bfloat16* __restrict__ Ah,
                                                __nv_bfloat16* __restrict__ Al,
                                                const __nv_bfloat16* __restrict__ Bh,
                                                const __nv_bfloat16* __restrict__ Bl,
                                                int ldb, float* __restrict__ scr, int lane) {
#pragma unroll
    for (int s = 0; s < 2; s++) {
        wmma::fragment<wmma::accumulator, 16, 16, 16, float> c[NTT];
#pragma unroll
        for (int nt = 0; nt < NTT; nt++) wmma::fill_fragment(c[nt], 0.0f);
#pragma unroll
        for (int kt = 0; kt < KT; kt++) {
            wmma::fragment<wmma::matrix_a, 16, 16, 16, __nv_bfloat16, wmma::row_major> ah, al;
            wmma::load_matrix_sync(ah, Ah + (s * 16) * A_STRIDE + kt * 16, A_STRIDE);
            wmma::load_matrix_sync(al, Al + (s * 16) * A_STRIDE + kt * 16, A_STRIDE);
#pragma unroll
            for (int nt = 0; nt < NTT; nt++) {
                wmma::fragment<wmma::matrix_b, 16, 16, 16, __nv_bfloat16, wmma::row_major> bh, bl;
                wmma::load_matrix_sync(bh, Bh + (kt * 16) * ldb + nt * 16, ldb);
                wmma::mma_sync(c[nt], ah, bh, c[nt]);
                wmma::mma_sync(c[nt], al, bh, c[nt]);
                wmma::load_matrix_sync(bl, Bl + (kt * 16) * ldb + nt * 16, ldb);
                wmma::mma_sync(c[nt], ah, bl, c[nt]);
            }
        }
        // epilogue: two 16x16 tiles at a time through fp32 scratch (stride 32)
#pragma unroll
        for (int pp = 0; pp < NTT; pp += 2) {
            wmma::store_matrix_sync(scr, c[pp], 32, wmma::mem_row_major);
            wmma::store_matrix_sync(scr + 16, c[pp + 1], 32, wmma::mem_row_major);
            __syncwarp();
            int r = lane >> 1, co = (lane & 1) * 16;
            const float* src = scr + r * 32 + co;
            uint32_t* dh = (uint32_t*)((char*)Ah + ((s * 16 + r) * A_STRIDE + pp * 16 + co) * 2);
            uint32_t* dl = (uint32_t*)((char*)Al + ((s * 16 + r) * A_STRIDE + pp * 16 + co) * 2);
#pragma unroll
            for (int j = 0; j < 8; j++) {
                float v0 = fmaxf(src[2 * j + 0], 0.0f);
                float v1 = fmaxf(src[2 * j + 1], 0.0f);
                __nv_bfloat162 h2 = __floats2bfloat162_rn(v0, v1);
                float2 hf = __bfloat1622float2(h2);
                __nv_bfloat162 l2 = __floats2bfloat162_rn(v0 - hf.x, v1 - hf.y);
                dh[j] = *reinterpret_cast<uint32_t*>(&h2);
                dl[j] = *reinterpret_cast<uint32_t*>(&l2);
            }
            __syncwarp();
        }
    }
}

__global__ void repack3_kernel(const float* __restrict__ wr3) {
    int i = blockIdx.x * blockDim.x + threadIdx.x;
    if (i >= 256) return;
    int r = i >> 2, c = i & 3;
    g_w3[i] = (c < 3) ? wr3[r * 3 + c] : 0.0f;
}

extern __shared__ char smem[];

__global__ __launch_bounds__(NT, 1) void nerf_kernel(
    const float* __restrict__ xyz, const float* __restrict__ dir,
    const float* __restrict__ table,
    const float* __restrict__ ws1, const float* __restrict__ ws2,
    const float* __restrict__ wr1, const float* __restrict__ wr2,
    float* __restrict__ out, int N) {
    const int tid = threadIdx.x;
    const int lane = tid & 31;
    const int w = tid >> 5;

    // ---- stage weights to smem as bf16 hi/lo, row-major [k][n] with padding ----
#define STAGE(DH, DL, ROWS, STR, NACT, SRC, NSTR)                                 \
    for (int i = tid; i < (ROWS) * (STR); i += NT) {                              \
        int k = i / (STR), n = i - k * (STR);                                     \
        float v = (n < (NACT)) ? SRC[k * (NSTR) + n] : 0.0f;                      \
        __nv_bfloat16 bh = __float2bfloat16(v);                                   \
        __nv_bfloat16 bl = __float2bfloat16(v - __bfloat162float(bh));            \
        ((__nv_bfloat16*)(smem + (DH)))[i] = bh;                                  \
        ((__nv_bfloat16*)(smem + (DL)))[i] = bl;                                  \
    }
    STAGE(SM_WS1H, SM_WS1L, 32, 72, 64, ws1, 64)
    STAGE(SM_WS2H, SM_WS2L, 64, 40, 17, ws2, 17)
    STAGE(SM_WR1H, SM_WR1L, 32, 72, 64, wr1, 64)
    STAGE(SM_WR2H, SM_WR2L, 64, 72, 64, wr2, 64)
#undef STAGE
    __syncthreads();

    __nv_bfloat16* Ah = (__nv_bfloat16*)(smem + SM_WARP0 + w * WARP_BYTES);
    __nv_bfloat16* Al = (__nv_bfloat16*)(smem + SM_WARP0 + w * WARP_BYTES + 4608);
    float* scr = (float*)(smem + SM_WARP0 + w * WARP_BYTES + 9216);
    uint32_t* arowh = (uint32_t*)((char*)Ah + lane * (A_STRIDE * 2));
    uint32_t* arowl = (uint32_t*)((char*)Al + lane * (A_STRIDE * 2));

    const __nv_bfloat16* WS1H = (const __nv_bfloat16*)(smem + SM_WS1H);
    const __nv_bfloat16* WS1L = (const __nv_bfloat16*)(smem + SM_WS1L);
    const __nv_bfloat16* WS2H = (const __nv_bfloat16*)(smem + SM_WS2H);
    const __nv_bfloat16* WS2L = (const __nv_bfloat16*)(smem + SM_WS2L);
    const __nv_bfloat16* WR1H = (const __nv_bfloat16*)(smem + SM_WR1H);
    const __nv_bfloat16* WR1L = (const __nv_bfloat16*)(smem + SM_WR1L);
    const __nv_bfloat16* WR2H = (const __nv_bfloat16*)(smem + SM_WR2H);
    const __nv_bfloat16* WR2L = (const __nv_bfloat16*)(smem + SM_WR2L);

    // helper to write a fp32 value as hi/lo bf16x2 pair into this thread's row
#define PUT2(idx, v0, v1)                                                         \
    do {                                                                          \
        __nv_bfloat162 _h2 = __floats2bfloat162_rn((v0), (v1));                   \
        float2 _hf = __bfloat1622float2(_h2);                                     \
        __nv_bfloat162 _l2 = __floats2bfloat162_rn((v0) - _hf.x, (v1) - _hf.y);   \
        arowh[idx] = *reinterpret_cast<uint32_t*>(&_h2);                          \
        arowl[idx] = *reinterpret_cast<uint32_t*>(&_l2);                          \
    } while (0)

#pragma unroll 1
    for (int it = 0; it < T_ITER; it++) {
        const int pbase = (blockIdx.x * T_ITER + it) * NT;
        if (pbase >= N) break;
        const int gid = pbase + tid;
        const bool valid = gid < N;
        const float px = valid ? xyz[3 * gid + 0] : 0.0f;
        const float py = valid ? xyz[3 * gid + 1] : 0.0f;
        const float pz = valid ? xyz[3 * gid + 2] : 0.0f;

        // ---- hash-grid encode -> A row `lane`, cols 0..31 (hi/lo bf16) ----
#pragma unroll 1
        for (int l = 0; l < 5; l++) {
            unsigned res = c_res[l];
            float fr = (float)res;
            float fx = px * fr, fy = py * fr, fz = pz * fr;
            float bx = floorf(fx), by = floorf(fy), bz = floorf(fz);
            float wx = fx - bx, wy = fy - by, wz = fz - bz;
            unsigned x0 = (unsigned)bx, y0 = (unsigned)by, z0 = (unsigned)bz;
            unsigned s = res + 1u, s2 = s * s;
            unsigned b = x0 + y0 * s + z0 * s2;
            const float2* tbl = (const float2*)table + (size_t)l * TSIZE;
            float2 c0 = __ldg(tbl + b), c1 = __ldg(tbl + b + 1u);
            float2 c2 = __ldg(tbl + b + s), c3 = __ldg(tbl + b + s + 1u);
            float2 c4 = __ldg(tbl + b + s2), c5 = __ldg(tbl + b + s2 + 1u);
            float2 c6 = __ldg(tbl + b + s2 + s), c7 = __ldg(tbl + b + s2 + s + 1u);
            float ux = 1.0f - wx, uy = 1.0f - wy, uz = 1.0f - wz;
            float w00 = ux * uy, w10 = wx * uy, w01 = ux * wy, w11 = wx * wy;
            float f0 = uz * (c0.x * w00 + c1.x * w10 + c2.x * w01 + c3.x * w11) +
                       wz * (c4.x * w00 + c5.x * w10 + c6.x * w01 + c7.x * w11);
            float f1 = uz * (c0.y * w00 + c1.y * w10 + c2.y * w01 + c3.y * w11) +
                       wz * (c4.y * w00 + c5.y * w10 + c6.y * w01 + c7.y * w11);
            PUT2(l, f0, f1);
        }
#pragma unroll 1
        for (int l = 5; l < 16; l++) {
            unsigned res = c_res[l];
            float fr = (float)res;
            float fx = px * fr, fy = py * fr, fz = pz * fr;
            float bx = floorf(fx), by = floorf(fy), bz = floorf(fz);
            float wx = fx - bx, wy = fy - by, wz = fz - bz;
            unsigned x0 = (unsigned)bx, y0 = (unsigned)by, z0 = (unsigned)bz;
            unsigned x1 = x0 + 1u;
            unsigned hy0 = y0 * 2654435761u, hy1 = hy0 + 2654435761u;
            unsigned hz0 = z0 * 805459861u, hz1 = hz0 + 805459861u;
            unsigned i0 = (x0 ^ hy0 ^ hz0) & TMASK, i1 = (x1 ^ hy0 ^ hz0) & TMASK;
            unsigned i2 = (x0 ^ hy1 ^ hz0) & TMASK, i3 = (x1 ^ hy1 ^ hz0) & TMASK;
            unsigned i4 = (x0 ^ hy0 ^ hz1) & TMASK, i5 = (x1 ^ hy0 ^ hz1) & TMASK;
            unsigned i6 = (x0 ^ hy1 ^ hz1) & TMASK, i7 = (x1 ^ hy1 ^ hz1) & TMASK;
            const float2* tbl = (const float2*)table + (size_t)l * TSIZE;
            float2 c0 = __ldg(tbl + i0), c1 = __ldg(tbl + i1), c2 = __ldg(tbl + i2), c3 = __ldg(tbl + i3);
            float2 c4 = __ldg(tbl + i4), c5 = __ldg(tbl + i5), c6 = __ldg(tbl + i6), c7 = __ldg(tbl + i7);
            float ux = 1.0f - wx, uy = 1.0f - wy, uz = 1.0f - wz;
            float w00 = ux * uy, w10 = wx * uy, w01 = ux * wy, w11 = wx * wy;
            float f0 = uz * (c0.x * w00 + c1.x * w10 + c2.x * w01 + c3.x * w11) +
                       wz * (c4.x * w00 + c5.x * w10 + c6.x * w01 + c7.x * w11);
            float f1 = uz * (c0.y * w00 + c1.y * w10 + c2.y * w01 + c3.y * w11) +
                       wz * (c4.y * w00 + c5.y * w10 + c6.y * w01 + c7.y * w11);
            PUT2(l, f0, f1);
        }
        __syncwarp();

        // ---- L1: 32 -> 64, relu ----
        dense_wmma_relu<2, 4>(Ah, Al, WS1H, WS1L, 72, scr, lane);

        // ---- L2: 64 -> 32(17 real), sigma + geo_feat (no relu on geo) ----
#pragma unroll
        for (int s = 0; s < 2; s++) {
            wmma::fragment<wmma::accumulator, 16, 16, 16, float> c[2];
            wmma::fill_fragment(c[0], 0.0f);
            wmma::fill_fragment(c[1], 0.0f);
#pragma unroll
            for (int kt = 0; kt < 4; kt++) {
                wmma::fragment<wmma::matrix_a, 16, 16, 16, __nv_bfloat16, wmma::row_major> ah, al;
                wmma::load_matrix_sync(ah, Ah + (s * 16) * A_STRIDE + kt * 16, A_STRIDE);
                wmma::load_matrix_sync(al, Al + (s * 16) * A_STRIDE + kt * 16, A_STRIDE);
#pragma unroll
                for (int nt = 0; nt < 2; nt++) {
                    wmma::fragment<wmma::matrix_b, 16, 16, 16, __nv_bfloat16, wmma::row_major> bh, bl;
                    wmma::load_matrix_sync(bh, WS2H + (kt * 16) * 40 + nt * 16, 40);
                    wmma::mma_sync(c[nt], ah, bh, c[nt]);
                    wmma::mma_sync(c[nt], al, bh, c[nt]);
                    wmma::load_matrix_sync(bl, WS2L + (kt * 16) * 40 + nt * 16, 40);
                    wmma::mma_sync(c[nt], ah, bl, c[nt]);
                }
            }
            wmma::store_matrix_sync(scr, c[0], 32, wmma::mem_row_major);
            wmma::store_matrix_sync(scr + 16, c[1], 32, wmma::mem_row_major);
            __syncwarp();
            {
                int r = lane >> 1, co = (lane & 1) * 16;
#pragma unroll
                for (int j = 0; j < 16; j++) {
                    int cgl = co + j;  // global output col 0..31
                    float v = scr[r * 32 + cgl];
                    if (cgl == 0) {
                        int pt = pbase + w * 32 + s * 16 + r;
                        if (pt < N) out[(size_t)3 * N + pt] = fmaxf(v, 0.0f);
                    } else if (cgl <= 16) {
                        // geometry col cgl -> geo_feat[cgl-1] -> A col 15+cgl (hi/lo)
                        __nv_bfloat16 bh = __float2bfloat16(v);
                        __nv_bfloat16 bl = __float2bfloat16(v - __bfloat162float(bh));
                        Ah[(s * 16 + r) * A_STRIDE + 15 + cgl] = bh;
                        Al[(s * 16 + r) * A_STRIDE + 15 + cgl] = bl;
                    }
                }
            }
            __syncwarp();
        }

        // ---- SH deg-4 of dir -> A cols 0..15 (row `lane`, hi/lo) ----
        {
            const float x = (valid ? dir[3 * gid + 0] : 0.5f) * 2.0f - 1.0f;
            const float y = (valid ? dir[3 * gid + 1] : 0.5f) * 2.0f - 1.0f;
            const float z = (valid ? dir[3 * gid + 2] : 0.5f) * 2.0f - 1.0f;
            float x2 = x * x, y2 = y * y, z2 = z * z;
            float xy = x * y, yz = y * z, xz = x * z;
            float sh[16];
            sh[0] = 0.28209479177387814f;
            sh[1] = -0.48860251190291987f * y;
            sh[2] = 0.48860251190291987f * z;
            sh[3] = -0.48860251190291987f * x;
            sh[4] = 1.0925484305920792f * xy;
            sh[5] = -1.0925484305920792f * yz;
            sh[6] = 0.94617469575756f * z2 - 0.31539156525252f;
            sh[7] = -1.0925484305920792f * xz;
            sh[8] = 0.5462742152960396f * (x2 - y2);
            sh[9] = 0.5900435899266435f * y * (-3.0f * x2 + y2);
            sh[10] = 2.890611442640554f * xy * z;
            sh[11] = 0.4570457994644657f * y * (1.0f - 5.0f * z2);
            sh[12] = 0.3731763325901154f * z * (5.0f * z2 - 3.0f);
            sh[13] = 0.4570457994644657f * x * (1.0f - 5.0f * z2);
            sh[14] = 1.445305721320277f * z * (x2 - y2);
            sh[15] = 0.5900435899266435f * x * (-x2 + 3.0f * y2);
#pragma unroll
            for (int j = 0; j < 8; j++) PUT2(j, sh[2 * j], sh[2 * j + 1]);
        }
        __syncwarp();

        // ---- L3: 32 -> 64, relu ----
        dense_wmma_relu<2, 4>(Ah, Al, WR1H, WR1L, 72, scr, lane);
        // ---- L4: 64 -> 64, relu ----
        dense_wmma_relu<4, 4>(Ah, Al, WR2H, WR2L, 72, scr, lane);

        // ---- final: 64 -> 3 scalar (wr3 in constant), sigmoid ----
        {
            float a0 = 0.0f, a1 = 0.0f, a2 = 0.0f;
#pragma unroll
            for (int c = 0; c < 32; c++) {
                uint32_t uh = arowh[c], ul = arowl[c];
                __nv_bfloat162 ph = *reinterpret_cast<__nv_bfloat162*>(&uh);
                __nv_bfloat162 pl = *reinterpret_cast<__nv_bfloat162*>(&ul);
                float2 fh = __bfloat1622float2(ph);
                float2 fl = __bfloat1622float2(pl);
                float v0 = fh.x + fl.x, v1 = fh.y + fl.y;
                a0 = fmaf(v0, c_w3[4 * (2 * c) + 0], a0);
                a1 = fmaf(v0, c_w3[4 * (2 * c) + 1], a1);
                a2 = fmaf(v0, c_w3[4 * (2 * c) + 2], a2);
                a0 = fmaf(v1, c_w3[4 * (2 * c + 1) + 0], a0);
                a1 = fmaf(v1, c_w3[4 * (2 * c + 1) + 1], a1);
                a2 = fmaf(v1, c_w3[4 * (2 * c + 1) + 2], a2);
            }
            if (valid) {
                out[3 * gid + 0] = sigmoidf_(a0);
                out[3 * gid + 1] = sigmoidf_(a1);
                out[3 * gid + 2] = sigmoidf_(a2);
            }
        }
        __syncwarp();
    }
#undef PUT2
}

extern "C" void kernel_launch(void* const* d_in, const int* in_sizes, int n_in,
                              void* d_out, int out_size) {
    const float* xyz = (const float*)d_in[0];
    const float* dir = (const float*)d_in[1];
    const float* table = (const float*)d_in[2];
    const float* ws1 = (const float*)d_in[3];
    const float* ws2 = (const float*)d_in[4];
    const float* wr1 = (const float*)d_in[5];
    const float* wr2 = (const float*)d_in[6];
    const float* wr3 = (const float*)d_in[7];
    float* out = (float*)d_out;
    int N = in_sizes[0] / 3;
    (void)n_in; (void)out_size;

    repack3_kernel<<<1, 256>>>(wr3);
    void* p3 = nullptr;
    cudaGetSymbolAddress(&p3, g_w3);
    cudaMemcpyToSymbolAsync(c_w3, p3, 256 * sizeof(float), 0, cudaMemcpyDeviceToDevice, 0);

    cudaFuncSetAttribute(nerf_kernel, cudaFuncAttributeMaxDynamicSharedMemorySize, SMEM_BYTES);
    int tiles = (N + NT - 1) / NT;
    int grid = (tiles + T_ITER - 1) / T_ITER;
    nerf_kernel<<<grid, NT, SMEM_BYTES>>>(xyz, dir, table, ws1, ws2, wr1, wr2, out, N);
}

// round 9
// speedup vs baseline: 1.4801x; 1.4801x over previous
#include <cuda_runtime.h>

#define NT 256
#define TSIZE (1u << 19)
#define TMASK (TSIZE - 1u)

// floor(16 * 1.3819^l), l = 0..15 (precomputed in double; matches numpy)
__constant__ unsigned c_res[16] = {16u, 22u, 30u, 42u, 58u, 80u, 111u, 153u,
                                   212u, 294u, 406u, 561u, 775u, 1072u, 1481u, 2047u};

// ---- packed weight layout in constant memory (float offsets) ----
#define CW_WS1 0
#define CW_WS2 2048
#define CW_WR1 3328
#define CW_WR2 5376
#define CW_WR3 9472
#define CW_TOTAL 9728

__constant__ __align__(16) float c_w[CW_TOTAL];
__device__ __align__(16) float g_pack[CW_TOTAL];

// activation scratch: 32 feature-pairs (float2) x NT threads = 64KB
#define SMEM_BYTES (32 * NT * 8)

__device__ __forceinline__ float sigmoidf_(float x) { return 1.0f / (1.0f + __expf(-x)); }

__device__ __forceinline__ unsigned long long pack2(float x, float y) {
    unsigned long long r;
    asm("mov.b64 %0, {%1, %2};" : "=l"(r) : "f"(x), "f"(y));
    return r;
}
__device__ __forceinline__ void unpack2(unsigned long long v, float& x, float& y) {
    asm("mov.b64 {%0, %1}, %2;" : "=f"(x), "=f"(y) : "l"(v));
}
// packed dual FMA: d = a * b + d  (two fp32 rn-FMAs, one issue)
__device__ __forceinline__ void ffma2(unsigned long long& d, unsigned long long a,
                                      unsigned long long b) {
    asm("fma.rn.f32x2 %0, %1, %2, %0;" : "+l"(d) : "l"(a), "l"(b));
}

// Dense layer: KIN inputs read from per-thread smem activations stored as float2
// feature-pairs (stride NT float2s, conflict-free). Weights from __constant__
// (uniform address -> uniform-const port, off the L1 crossbar). JP2 = 16B weight
// chunks per row (J = 4*JP2 outputs). Accumulates 2*JP2 packed f32x2 pairs.
template <int KIN, int JP2, int WBASE>
__device__ __forceinline__ void dense_c(const float2* __restrict__ act2,
                                        unsigned long long* __restrict__ acc) {
#pragma unroll
    for (int j = 0; j < 2 * JP2; j++) acc[j] = 0ull;
#pragma unroll 2
    for (int kk = 0; kk < KIN / 2; kk++) {
        float2 av = act2[kk * NT];
        unsigned long long a0 = pack2(av.x, av.x);
        unsigned long long a1 = pack2(av.y, av.y);
        const ulonglong2* w0 = (const ulonglong2*)(c_w + WBASE + (2 * kk) * (4 * JP2));
        const ulonglong2* w1 = (const ulonglong2*)(c_w + WBASE + (2 * kk + 1) * (4 * JP2));
#pragma unroll
        for (int j = 0; j < JP2; j++) {
            ulonglong2 wv0 = w0[j];
            ffma2(acc[2 * j + 0], a0, wv0.x);
            ffma2(acc[2 * j + 1], a0, wv0.y);
        }
#pragma unroll
        for (int j = 0; j < JP2; j++) {
            ulonglong2 wv1 = w1[j];
            ffma2(acc[2 * j + 0], a1, wv1.x);
            ffma2(acc[2 * j + 1], a1, wv1.y);
        }
    }
}

// repack weights (with zero padding) into one device buffer for the D2D copy into c_w
__global__ void repack_kernel(const float* __restrict__ ws1, const float* __restrict__ ws2,
                              const float* __restrict__ wr1, const float* __restrict__ wr2,
                              const float* __restrict__ wr3) {
    int i = blockIdx.x * blockDim.x + threadIdx.x;
    if (i >= CW_TOTAL) return;
    float v;
    if (i < CW_WS2) {
        v = ws1[i];
    } else if (i < CW_WR1) {
        int j = i - CW_WS2;
        int r = j / 20, c = j - r * 20;
        v = (c < 17) ? ws2[r * 17 + c] : 0.0f;
    } else if (i < CW_WR2) {
        v = wr1[i - CW_WR1];
    } else if (i < CW_WR3) {
        v = wr2[i - CW_WR2];
    } else {
        int j = i - CW_WR3;
        int r = j >> 2, c = j & 3;
        v = (c < 3) ? wr3[r * 3 + c] : 0.0f;
    }
    g_pack[i] = v;
}

extern __shared__ float2 smem2[];

__global__ __launch_bounds__(NT, 3) void nerf_kernel(
    const float* __restrict__ xyz, const float* __restrict__ dir,
    const float* __restrict__ table,
    float* __restrict__ out, int N) {
    const int t = threadIdx.x;
    const int gid = blockIdx.x * NT + t;
    if (gid >= N) return;

    float2* act2 = smem2 + t;  // per-thread activation column (float2 pairs, stride NT)

    const float px = xyz[3 * gid + 0];
    const float py = xyz[3 * gid + 1];
    const float pz = xyz[3 * gid + 2];
    // hoist dir load: overlaps the gather phase
    const float dx = dir[3 * gid + 0];
    const float dy = dir[3 * gid + 1];
    const float dz = dir[3 * gid + 2];

    // ---- hash-grid encode: dense levels 0..4 ----
#pragma unroll 1
    for (int l = 0; l < 5; l++) {
        unsigned res = c_res[l];
        float fr = (float)res;
        float fx = px * fr, fy = py * fr, fz = pz * fr;
        float bx = floorf(fx), by = floorf(fy), bz = floorf(fz);
        float wx = fx - bx, wy = fy - by, wz = fz - bz;
        unsigned x0 = (unsigned)bx, y0 = (unsigned)by, z0 = (unsigned)bz;
        unsigned s = res + 1u, s2 = s * s;
        unsigned b = x0 + y0 * s + z0 * s2;
        unsigned i0 = b, i1 = b + 1u, i2 = b + s, i3 = b + s + 1u;
        unsigned i4 = b + s2, i5 = b + s2 + 1u, i6 = b + s2 + s, i7 = b + s2 + s + 1u;

        const float2* tb = (const float2*)table + (size_t)l * TSIZE;
        float2 c0 = __ldg(tb + i0), c1 = __ldg(tb + i1), c2 = __ldg(tb + i2), c3 = __ldg(tb + i3);
        float2 c4 = __ldg(tb + i4), c5 = __ldg(tb + i5), c6 = __ldg(tb + i6), c7 = __ldg(tb + i7);

        float ux = 1.0f - wx, uy = 1.0f - wy, uz = 1.0f - wz;
        float w00 = ux * uy, w10 = wx * uy, w01 = ux * wy, w11 = wx * wy;
        float f0 = uz * (c0.x * w00 + c1.x * w10 + c2.x * w01 + c3.x * w11) +
                   wz * (c4.x * w00 + c5.x * w10 + c6.x * w01 + c7.x * w11);
        float f1 = uz * (c0.y * w00 + c1.y * w10 + c2.y * w01 + c3.y * w11) +
                   wz * (c4.y * w00 + c5.y * w10 + c6.y * w01 + c7.y * w11);
        act2[l * NT] = make_float2(f0, f1);
    }

    // ---- hash-grid encode: hashed levels 5..15 ----
#pragma unroll 1
    for (int l = 5; l < 16; l++) {
        unsigned res = c_res[l];
        float fr = (float)res;
        float fx = px * fr, fy = py * fr, fz = pz * fr;
        float bx = floorf(fx), by = floorf(fy), bz = floorf(fz);
        float wx = fx - bx, wy = fy - by, wz = fz - bz;
        unsigned x0 = (unsigned)bx, y0 = (unsigned)by, z0 = (unsigned)bz;
        unsigned x1 = x0 + 1u;
        unsigned hy0 = y0 * 2654435761u, hy1 = hy0 + 2654435761u;
        unsigned hz0 = z0 * 805459861u, hz1 = hz0 + 805459861u;
        unsigned i0 = (x0 ^ hy0 ^ hz0) & TMASK;
        unsigned i1 = (x1 ^ hy0 ^ hz0) & TMASK;
        unsigned i2 = (x0 ^ hy1 ^ hz0) & TMASK;
        unsigned i3 = (x1 ^ hy1 ^ hz0) & TMASK;
        unsigned i4 = (x0 ^ hy0 ^ hz1) & TMASK;
        unsigned i5 = (x1 ^ hy0 ^ hz1) & TMASK;
        unsigned i6 = (x0 ^ hy1 ^ hz1) & TMASK;
        unsigned i7 = (x1 ^ hy1 ^ hz1) & TMASK;

        const float2* tb = (const float2*)table + (size_t)l * TSIZE;
        float2 c0 = __ldg(tb + i0), c1 = __ldg(tb + i1), c2 = __ldg(tb + i2), c3 = __ldg(tb + i3);
        float2 c4 = __ldg(tb + i4), c5 = __ldg(tb + i5), c6 = __ldg(tb + i6), c7 = __ldg(tb + i7);

        float ux = 1.0f - wx, uy = 1.0f - wy, uz = 1.0f - wz;
        float w00 = ux * uy, w10 = wx * uy, w01 = ux * wy, w11 = wx * wy;
        float f0 = uz * (c0.x * w00 + c1.x * w10 + c2.x * w01 + c3.x * w11) +
                   wz * (c4.x * w00 + c5.x * w10 + c6.x * w01 + c7.x * w11);
        float f1 = uz * (c0.y * w00 + c1.y * w10 + c2.y * w01 + c3.y * w11) +
                   wz * (c4.y * w00 + c5.y * w10 + c6.y * w01 + c7.y * w11);
        act2[l * NT] = make_float2(f0, f1);
    }

    unsigned long long acc[32];

    // ---- sigma MLP: 32 -> 64 (relu) -> 20(17) ----
    dense_c<32, 16, CW_WS1>(act2, acc);
#pragma unroll
    for (int j = 0; j < 32; j++) {
        float lo, hi;
        unpack2(acc[j], lo, hi);
        act2[j * NT] = make_float2(fmaxf(lo, 0.0f), fmaxf(hi, 0.0f));
    }

    dense_c<64, 5, CW_WS2>(act2, acc);
    float geo[20];
#pragma unroll
    for (int j = 0; j < 10; j++) unpack2(acc[j], geo[2 * j], geo[2 * j + 1]);
    float sigma_raw = geo[0];

    // ---- SH deg-4 direction encoding ----
    const float x = dx * 2.0f - 1.0f;
    const float y = dy * 2.0f - 1.0f;
    const float z = dz * 2.0f - 1.0f;
    float x2 = x * x, y2 = y * y, z2 = z * z;
    float xy = x * y, yz = y * z, xz = x * z;
    act2[0 * NT] = make_float2(0.28209479177387814f, -0.48860251190291987f * y);
    act2[1 * NT] = make_float2(0.48860251190291987f * z, -0.48860251190291987f * x);
    act2[2 * NT] = make_float2(1.0925484305920792f * xy, -1.0925484305920792f * yz);
    act2[3 * NT] = make_float2(0.94617469575756f * z2 - 0.31539156525252f,
                               -1.0925484305920792f * xz);
    act2[4 * NT] = make_float2(0.5462742152960396f * (x2 - y2),
                               0.5900435899266435f * y * (-3.0f * x2 + y2));
    act2[5 * NT] = make_float2(2.890611442640554f * xy * z,
                               0.4570457994644657f * y * (1.0f - 5.0f * z2));
    act2[6 * NT] = make_float2(0.3731763325901154f * z * (5.0f * z2 - 3.0f),
                               0.4570457994644657f * x * (1.0f - 5.0f * z2));
    act2[7 * NT] = make_float2(1.445305721320277f * z * (x2 - y2),
                               0.5900435899266435f * x * (-x2 + 3.0f * y2));
#pragma unroll
    for (int j = 0; j < 8; j++)
        act2[(8 + j) * NT] = make_float2(geo[1 + 2 * j], geo[2 + 2 * j]);

    // ---- rgb MLP: 32 -> 64 (relu) -> 64 (relu) -> 4(3) ----
    dense_c<32, 16, CW_WR1>(act2, acc);
#pragma unroll
    for (int j = 0; j < 32; j++) {
        float lo, hi;
        unpack2(acc[j], lo, hi);
        act2[j * NT] = make_float2(fmaxf(lo, 0.0f), fmaxf(hi, 0.0f));
    }

    dense_c<64, 16, CW_WR2>(act2, acc);
#pragma unroll
    for (int j = 0; j < 32; j++) {
        float lo, hi;
        unpack2(acc[j], lo, hi);
        act2[j * NT] = make_float2(fmaxf(lo, 0.0f), fmaxf(hi, 0.0f));
    }

    dense_c<64, 1, CW_WR3>(act2, acc);
    float r0, r1, r2, r3;
    unpack2(acc[0], r0, r1);
    unpack2(acc[1], r2, r3);

    out[3 * gid + 0] = sigmoidf_(r0);
    out[3 * gid + 1] = sigmoidf_(r1);
    out[3 * gid + 2] = sigmoidf_(r2);
    out[(size_t)3 * N + gid] = fmaxf(sigma_raw, 0.0f);
}

extern "C" void kernel_launch(void* const* d_in, const int* in_sizes, int n_in,
                              void* d_out, int out_size) {
    const float* xyz = (const float*)d_in[0];
    const float* dir = (const float*)d_in[1];
    const float* table = (const float*)d_in[2];
    const float* ws1 = (const float*)d_in[3];
    const float* ws2 = (const float*)d_in[4];
    const float* wr1 = (const float*)d_in[5];
    const float* wr2 = (const float*)d_in[6];
    const float* wr3 = (const float*)d_in[7];
    float* out = (float*)d_out;
    int N = in_sizes[0] / 3;
    (void)n_in; (void)out_size;

    // stage weights: repack (pad) -> device buffer -> constant bank (D2D, capturable)
    repack_kernel<<<(CW_TOTAL + 255) / 256, 256>>>(ws1, ws2, wr1, wr2, wr3);
    void* packed_ptr = nullptr;
    cudaGetSymbolAddress(&packed_ptr, g_pack);
    cudaMemcpyToSymbolAsync(c_w, packed_ptr, CW_TOTAL * sizeof(float), 0,
                            cudaMemcpyDeviceToDevice, 0);

    cudaFuncSetAttribute(nerf_kernel, cudaFuncAttributeMaxDynamicSharedMemorySize, SMEM_BYTES);
    int grid = (N + NT - 1) / NT;
    nerf_kernel<<<grid, NT, SMEM_BYTES>>>(xyz, dir, table, out, N);
}

// round 10
// speedup vs baseline: 1.8446x; 1.2462x over previous
#include <cuda_runtime.h>

#define NT 256
#define TSIZE (1u << 19)
#define TMASK (TSIZE - 1u)

// floor(16 * 1.3819^l), l = 0..15 (compile-time constants; fully unrolled loops)
#define RES_LIST {16u, 22u, 30u, 42u, 58u, 80u, 111u, 153u, 212u, 294u, 406u, 561u, 775u, 1072u, 1481u, 2047u}

// ---- packed weight layout in constant memory (float offsets) ----
// ws1: 32x64  @ 0      (2048)
// ws2: 64x20  @ 2048   (1280)   cols 17..19 zero-padded
// wr1: 32x64  @ 3328   (2048)
// wr2: 64x64  @ 5376   (4096)
// wr3: 64x4   @ 9472   (256)    col 3 zero-padded
#define CW_WS1 0
#define CW_WS2 2048
#define CW_WR1 3328
#define CW_WR2 5376
#define CW_WR3 9472
#define CW_TOTAL 9728

__constant__ __align__(16) float c_w[CW_TOTAL];
__device__ __align__(16) float g_pack[CW_TOTAL];

// activation scratch: 64 features x NT threads
#define SMEM_FLOATS (64 * NT)
#define SMEM_BYTES (SMEM_FLOATS * 4)

__device__ __forceinline__ float sigmoidf_(float x) { return 1.0f / (1.0f + __expf(-x)); }

__device__ __forceinline__ unsigned long long pack2(float x, float y) {
    unsigned long long r;
    asm("mov.b64 %0, {%1, %2};" : "=l"(r) : "f"(x), "f"(y));
    return r;
}
__device__ __forceinline__ void unpack2(unsigned long long v, float& x, float& y) {
    asm("mov.b64 {%0, %1}, %2;" : "=f"(x), "=f"(y) : "l"(v));
}
// packed dual FMA: d = a * b + d  (two fp32 rn-FMAs, one issue)
__device__ __forceinline__ void ffma2(unsigned long long& d, unsigned long long a,
                                      unsigned long long b) {
    asm("fma.rn.f32x2 %0, %1, %2, %0;" : "+l"(d) : "l"(a), "l"(b));
}

// Dense layer: KIN inputs from per-thread smem activations (stride NT, conflict-free),
// weights from __constant__ (uniform address -> uniform-const port, off the L1
// crossbar). JP2 = 16B weight chunks per row (J = 4*JP2 outputs). Accumulates into
// 2*JP2 packed f32x2 pairs via FFMA2.  (UNCHANGED from the 1159us R4 kernel.)
template <int KIN, int JP2, int WBASE>
__device__ __forceinline__ void dense_c(const float* __restrict__ act,
                                        unsigned long long* __restrict__ acc) {
#pragma unroll
    for (int j = 0; j < 2 * JP2; j++) acc[j] = 0ull;
#pragma unroll 4
    for (int k = 0; k < KIN; k++) {
        float a = act[k * NT];
        unsigned long long a2 = pack2(a, a);
        const ulonglong2* wr = (const ulonglong2*)(c_w + WBASE + k * (4 * JP2));
#pragma unroll
        for (int j = 0; j < JP2; j++) {
            ulonglong2 wv = wr[j];
            ffma2(acc[2 * j + 0], a2, wv.x);
            ffma2(acc[2 * j + 1], a2, wv.y);
        }
    }
}

// repack weights (with zero padding) into one device buffer for the D2D copy into c_w
__global__ void repack_kernel(const float* __restrict__ ws1, const float* __restrict__ ws2,
                              const float* __restrict__ wr1, const float* __restrict__ wr2,
                              const float* __restrict__ wr3) {
    int i = blockIdx.x * blockDim.x + threadIdx.x;
    if (i >= CW_TOTAL) return;
    float v;
    if (i < CW_WS2) {
        v = ws1[i];
    } else if (i < CW_WR1) {
        int j = i - CW_WS2;
        int r = j / 20, c = j - r * 20;
        v = (c < 17) ? ws2[r * 17 + c] : 0.0f;
    } else if (i < CW_WR2) {
        v = wr1[i - CW_WR1];
    } else if (i < CW_WR3) {
        v = wr2[i - CW_WR2];
    } else {
        int j = i - CW_WR3;
        int r = j >> 2, c = j & 3;
        v = (c < 3) ? wr3[r * 3 + c] : 0.0f;
    }
    g_pack[i] = v;
}

extern __shared__ float smem[];

__global__ __launch_bounds__(NT, 2) void nerf_kernel(
    const float* __restrict__ xyz, const float* __restrict__ dir,
    const float* __restrict__ table,
    float* __restrict__ out, int N) {
    const int t = threadIdx.x;
    const int gid = blockIdx.x * NT + t;
    if (gid >= N) return;

    float* act = smem + t;  // per-thread activation column, stride NT

    const float px = xyz[3 * gid + 0];
    const float py = xyz[3 * gid + 1];
    const float pz = xyz[3 * gid + 2];
    // hoist dir load: its latency hides under the gather phase
    const float dx = dir[3 * gid + 0];
    const float dy = dir[3 * gid + 1];
    const float dz = dir[3 * gid + 2];

    constexpr unsigned RESV[16] = RES_LIST;

    // ---- hash-grid encode: dense levels 0..4 (FULLY UNROLLED -> batched LDGs) ----
#pragma unroll
    for (int l = 0; l < 5; l++) {
        const unsigned res = RESV[l];
        const float fr = (float)res;
        float fx = px * fr, fy = py * fr, fz = pz * fr;
        float bx = floorf(fx), by = floorf(fy), bz = floorf(fz);
        float wx = fx - bx, wy = fy - by, wz = fz - bz;
        unsigned x0 = (unsigned)bx, y0 = (unsigned)by, z0 = (unsigned)bz;
        const unsigned s = res + 1u, s2 = s * s;
        unsigned b = x0 + y0 * s + z0 * s2;
        unsigned i0 = b, i1 = b + 1u, i2 = b + s, i3 = b + s + 1u;
        unsigned i4 = b + s2, i5 = b + s2 + 1u, i6 = b + s2 + s, i7 = b + s2 + s + 1u;

        const float2* tb = (const float2*)table + (size_t)l * TSIZE;
        float2 c0 = __ldg(tb + i0), c1 = __ldg(tb + i1), c2 = __ldg(tb + i2), c3 = __ldg(tb + i3);
        float2 c4 = __ldg(tb + i4), c5 = __ldg(tb + i5), c6 = __ldg(tb + i6), c7 = __ldg(tb + i7);

        float ux = 1.0f - wx, uy = 1.0f - wy, uz = 1.0f - wz;
        float w00 = ux * uy, w10 = wx * uy, w01 = ux * wy, w11 = wx * wy;
        float f0 = uz * (c0.x * w00 + c1.x * w10 + c2.x * w01 + c3.x * w11) +
                   wz * (c4.x * w00 + c5.x * w10 + c6.x * w01 + c7.x * w11);
        float f1 = uz * (c0.y * w00 + c1.y * w10 + c2.y * w01 + c3.y * w11) +
                   wz * (c4.y * w00 + c5.y * w10 + c6.y * w01 + c7.y * w11);
        act[(2 * l + 0) * NT] = f0;
        act[(2 * l + 1) * NT] = f1;
    }

    // ---- hash-grid encode: hashed levels 5..15 (FULLY UNROLLED -> batched LDGs) ----
#pragma unroll
    for (int l = 5; l < 16; l++) {
        const unsigned res = RESV[l];
        const float fr = (float)res;
        float fx = px * fr, fy = py * fr, fz = pz * fr;
        float bx = floorf(fx), by = floorf(fy), bz = floorf(fz);
        float wx = fx - bx, wy = fy - by, wz = fz - bz;
        unsigned x0 = (unsigned)bx, y0 = (unsigned)by, z0 = (unsigned)bz;
        unsigned x1 = x0 + 1u;
        unsigned hy0 = y0 * 2654435761u, hy1 = hy0 + 2654435761u;
        unsigned hz0 = z0 * 805459861u, hz1 = hz0 + 805459861u;
        unsigned i0 = (x0 ^ hy0 ^ hz0) & TMASK;
        unsigned i1 = (x1 ^ hy0 ^ hz0) & TMASK;
        unsigned i2 = (x0 ^ hy1 ^ hz0) & TMASK;
        unsigned i3 = (x1 ^ hy1 ^ hz0) & TMASK;
        unsigned i4 = (x0 ^ hy0 ^ hz1) & TMASK;
        unsigned i5 = (x1 ^ hy0 ^ hz1) & TMASK;
        unsigned i6 = (x0 ^ hy1 ^ hz1) & TMASK;
        unsigned i7 = (x1 ^ hy1 ^ hz1) & TMASK;

        const float2* tb = (const float2*)table + (size_t)l * TSIZE;
        float2 c0 = __ldg(tb + i0), c1 = __ldg(tb + i1), c2 = __ldg(tb + i2), c3 = __ldg(tb + i3);
        float2 c4 = __ldg(tb + i4), c5 = __ldg(tb + i5), c6 = __ldg(tb + i6), c7 = __ldg(tb + i7);

        float ux = 1.0f - wx, uy = 1.0f - wy, uz = 1.0f - wz;
        float w00 = ux * uy, w10 = wx * uy, w01 = ux * wy, w11 = wx * wy;
        float f0 = uz * (c0.x * w00 + c1.x * w10 + c2.x * w01 + c3.x * w11) +
                   wz * (c4.x * w00 + c5.x * w10 + c6.x * w01 + c7.x * w11);
        float f1 = uz * (c0.y * w00 + c1.y * w10 + c2.y * w01 + c3.y * w11) +
                   wz * (c4.y * w00 + c5.y * w10 + c6.y * w01 + c7.y * w11);
        act[(2 * l + 0) * NT] = f0;
        act[(2 * l + 1) * NT] = f1;
    }

    unsigned long long acc[32];

    // ---- sigma MLP: 32 -> 64 (relu) -> 20(17) ----
    dense_c<32, 16, CW_WS1>(act, acc);
#pragma unroll
    for (int j = 0; j < 32; j++) {
        float lo, hi;
        unpack2(acc[j], lo, hi);
        act[(2 * j + 0) * NT] = fmaxf(lo, 0.0f);
        act[(2 * j + 1) * NT] = fmaxf(hi, 0.0f);
    }

    dense_c<64, 5, CW_WS2>(act, acc);
    float geo[20];
#pragma unroll
    for (int j = 0; j < 10; j++) unpack2(acc[j], geo[2 * j], geo[2 * j + 1]);
    float sigma_raw = geo[0];

    // ---- SH deg-4 direction encoding ----
    const float x = dx * 2.0f - 1.0f;
    const float y = dy * 2.0f - 1.0f;
    const float z = dz * 2.0f - 1.0f;
    float x2 = x * x, y2 = y * y, z2 = z * z;
    float xy = x * y, yz = y * z, xz = x * z;
    act[0 * NT] = 0.28209479177387814f;
    act[1 * NT] = -0.48860251190291987f * y;
    act[2 * NT] = 0.48860251190291987f * z;
    act[3 * NT] = -0.48860251190291987f * x;
    act[4 * NT] = 1.0925484305920792f * xy;
    act[5 * NT] = -1.0925484305920792f * yz;
    act[6 * NT] = 0.94617469575756f * z2 - 0.31539156525252f;
    act[7 * NT] = -1.0925484305920792f * xz;
    act[8 * NT] = 0.5462742152960396f * (x2 - y2);
    act[9 * NT] = 0.5900435899266435f * y * (-3.0f * x2 + y2);
    act[10 * NT] = 2.890611442640554f * xy * z;
    act[11 * NT] = 0.4570457994644657f * y * (1.0f - 5.0f * z2);
    act[12 * NT] = 0.3731763325901154f * z * (5.0f * z2 - 3.0f);
    act[13 * NT] = 0.4570457994644657f * x * (1.0f - 5.0f * z2);
    act[14 * NT] = 1.445305721320277f * z * (x2 - y2);
    act[15 * NT] = 0.5900435899266435f * x * (-x2 + 3.0f * y2);
#pragma unroll
    for (int j = 0; j < 16; j++) act[(16 + j) * NT] = geo[1 + j];

    // ---- rgb MLP: 32 -> 64 (relu) -> 64 (relu) -> 4(3) ----
    dense_c<32, 16, CW_WR1>(act, acc);
#pragma unroll
    for (int j = 0; j < 32; j++) {
        float lo, hi;
        unpack2(acc[j], lo, hi);
        act[(2 * j + 0) * NT] = fmaxf(lo, 0.0f);
        act[(2 * j + 1) * NT] = fmaxf(hi, 0.0f);
    }

    dense_c<64, 16, CW_WR2>(act, acc);
#pragma unroll
    for (int j = 0; j < 32; j++) {
        float lo, hi;
        unpack2(acc[j], lo, hi);
        act[(2 * j + 0) * NT] = fmaxf(lo, 0.0f);
        act[(2 * j + 1) * NT] = fmaxf(hi, 0.0f);
    }

    dense_c<64, 1, CW_WR3>(act, acc);
    float r0, r1, r2, r3;
    unpack2(acc[0], r0, r1);
    unpack2(acc[1], r2, r3);

    out[3 * gid + 0] = sigmoidf_(r0);
    out[3 * gid + 1] = sigmoidf_(r1);
    out[3 * gid + 2] = sigmoidf_(r2);
    out[(size_t)3 * N + gid] = fmaxf(sigma_raw, 0.0f);
}

extern "C" void kernel_launch(void* const* d_in, const int* in_sizes, int n_in,
                              void* d_out, int out_size) {
    const float* xyz = (const float*)d_in[0];
    const float* dir = (const float*)d_in[1];
    const float* table = (const float*)d_in[2];
    const float* ws1 = (const float*)d_in[3];
    const float* ws2 = (const float*)d_in[4];
    const float* wr1 = (const float*)d_in[5];
    const float* wr2 = (const float*)d_in[6];
    const float* wr3 = (const float*)d_in[7];
    float* out = (float*)d_out;
    int N = in_sizes[0] / 3;
    (void)n_in; (void)out_size;

    // stage weights: repack (pad) -> device buffer -> constant bank (D2D, capturable)
    repack_kernel<<<(CW_TOTAL + 255) / 256, 256>>>(ws1, ws2, wr1, wr2, wr3);
    void* packed_ptr = nullptr;
    cudaGetSymbolAddress(&packed_ptr, g_pack);
    cudaMemcpyToSymbolAsync(c_w, packed_ptr, CW_TOTAL * sizeof(float), 0,
                            cudaMemcpyDeviceToDevice, 0);

    cudaFuncSetAttribute(nerf_kernel, cudaFuncAttributeMaxDynamicSharedMemorySize, SMEM_BYTES);
    int grid = (N + NT - 1) / NT;
    nerf_kernel<<<grid, NT, SMEM_BYTES>>>(xyz, dir, table, out, N);
}

// round 11
// speedup vs baseline: 1.9716x; 1.0689x over previous
#include <cuda_runtime.h>

#define NT 256
#define TSIZE (1u << 19)
#define TMASK (TSIZE - 1u)

// floor(16 * 1.3819^l), l = 0..15 (compile-time constants; fully unrolled loops)
#define RES_LIST {16u, 22u, 30u, 42u, 58u, 80u, 111u, 153u, 212u, 294u, 406u, 561u, 775u, 1072u, 1481u, 2047u}

// ---- packed weight layout in constant memory (float offsets) ----
// ws1: 32x64  @ 0      (2048)
// ws2: 64x20  @ 2048   (1280)   cols 17..19 zero-padded
// wr1: 32x64  @ 3328   (2048)
// wr2: 64x64  @ 5376   (4096)
// wr3: 64x4   @ 9472   (256)    col 3 zero-padded
#define CW_WS1 0
#define CW_WS2 2048
#define CW_WR1 3328
#define CW_WR2 5376
#define CW_WR3 9472
#define CW_TOTAL 9728

__constant__ __align__(16) float c_w[CW_TOTAL];
__device__ __align__(16) float g_pack[CW_TOTAL];

// activation scratch: 64 features x NT threads = 64KB (3 blocks -> 192KB <= 228KB)
#define SMEM_FLOATS (64 * NT)
#define SMEM_BYTES (SMEM_FLOATS * 4)

__device__ __forceinline__ float sigmoidf_(float x) { return 1.0f / (1.0f + __expf(-x)); }

__device__ __forceinline__ unsigned long long pack2(float x, float y) {
    unsigned long long r;
    asm("mov.b64 %0, {%1, %2};" : "=l"(r) : "f"(x), "f"(y));
    return r;
}
__device__ __forceinline__ void unpack2(unsigned long long v, float& x, float& y) {
    asm("mov.b64 {%0, %1}, %2;" : "=f"(x), "=f"(y) : "l"(v));
}
// packed dual FMA: d = a * b + d  (two fp32 rn-FMAs, one issue)
__device__ __forceinline__ void ffma2(unsigned long long& d, unsigned long long a,
                                      unsigned long long b) {
    asm("fma.rn.f32x2 %0, %1, %2, %0;" : "+l"(d) : "l"(a), "l"(b));
}

// Dense layer: KIN inputs from per-thread smem activations (stride NT, conflict-free),
// weights from __constant__ (uniform address -> uniform-const port, off the L1
// crossbar). JP2 = 16B weight chunks per row (J = 4*JP2 outputs). Accumulates into
// 2*JP2 packed f32x2 pairs via FFMA2.  (UNCHANGED from the 1159us R4 kernel.)
template <int KIN, int JP2, int WBASE>
__device__ __forceinline__ void dense_c(const float* __restrict__ act,
                                        unsigned long long* __restrict__ acc) {
#pragma unroll
    for (int j = 0; j < 2 * JP2; j++) acc[j] = 0ull;
#pragma unroll 4
    for (int k = 0; k < KIN; k++) {
        float a = act[k * NT];
        unsigned long long a2 = pack2(a, a);
        const ulonglong2* wr = (const ulonglong2*)(c_w + WBASE + k * (4 * JP2));
#pragma unroll
        for (int j = 0; j < JP2; j++) {
            ulonglong2 wv = wr[j];
            ffma2(acc[2 * j + 0], a2, wv.x);
            ffma2(acc[2 * j + 1], a2, wv.y);
        }
    }
}

// repack weights (with zero padding) into one device buffer for the D2D copy into c_w
__global__ void repack_kernel(const float* __restrict__ ws1, const float* __restrict__ ws2,
                              const float* __restrict__ wr1, const float* __restrict__ wr2,
                              const float* __restrict__ wr3) {
    int i = blockIdx.x * blockDim.x + threadIdx.x;
    if (i >= CW_TOTAL) return;
    float v;
    if (i < CW_WS2) {
        v = ws1[i];
    } else if (i < CW_WR1) {
        int j = i - CW_WS2;
        int r = j / 20, c = j - r * 20;
        v = (c < 17) ? ws2[r * 17 + c] : 0.0f;
    } else if (i < CW_WR2) {
        v = wr1[i - CW_WR1];
    } else if (i < CW_WR3) {
        v = wr2[i - CW_WR2];
    } else {
        int j = i - CW_WR3;
        int r = j >> 2, c = j & 3;
        v = (c < 3) ? wr3[r * 3 + c] : 0.0f;
    }
    g_pack[i] = v;
}

extern __shared__ float smem[];

// minBlocks=3 -> ptxas reg budget 85: keeps 3 CTAs/SM resident (24 warps) while
// the fully-unrolled encode batches gathers up to the register budget.
__global__ __launch_bounds__(NT, 3) void nerf_kernel(
    const float* __restrict__ xyz, const float* __restrict__ dir,
    const float* __restrict__ table,
    float* __restrict__ out, int N) {
    const int t = threadIdx.x;
    const int gid = blockIdx.x * NT + t;
    if (gid >= N) return;

    float* act = smem + t;  // per-thread activation column, stride NT

    const float px = xyz[3 * gid + 0];
    const float py = xyz[3 * gid + 1];
    const float pz = xyz[3 * gid + 2];
    // hoist dir load: its latency hides under the gather phase
    const float dx = dir[3 * gid + 0];
    const float dy = dir[3 * gid + 1];
    const float dz = dir[3 * gid + 2];

    constexpr unsigned RESV[16] = RES_LIST;

    // ---- hash-grid encode: dense levels 0..4 (unrolled -> batched LDGs) ----
#pragma unroll
    for (int l = 0; l < 5; l++) {
        const unsigned res = RESV[l];
        const float fr = (float)res;
        float fx = px * fr, fy = py * fr, fz = pz * fr;
        float bx = floorf(fx), by = floorf(fy), bz = floorf(fz);
        float wx = fx - bx, wy = fy - by, wz = fz - bz;
        unsigned x0 = (unsigned)bx, y0 = (unsigned)by, z0 = (unsigned)bz;
        const unsigned s = res + 1u, s2 = s * s;
        unsigned b = x0 + y0 * s + z0 * s2;
        unsigned i0 = b, i1 = b + 1u, i2 = b + s, i3 = b + s + 1u;
        unsigned i4 = b + s2, i5 = b + s2 + 1u, i6 = b + s2 + s, i7 = b + s2 + s + 1u;

        const float2* tb = (const float2*)table + (size_t)l * TSIZE;
        float2 c0 = __ldg(tb + i0), c1 = __ldg(tb + i1), c2 = __ldg(tb + i2), c3 = __ldg(tb + i3);
        float2 c4 = __ldg(tb + i4), c5 = __ldg(tb + i5), c6 = __ldg(tb + i6), c7 = __ldg(tb + i7);

        float ux = 1.0f - wx, uy = 1.0f - wy, uz = 1.0f - wz;
        float w00 = ux * uy, w10 = wx * uy, w01 = ux * wy, w11 = wx * wy;
        float f0 = uz * (c0.x * w00 + c1.x * w10 + c2.x * w01 + c3.x * w11) +
                   wz * (c4.x * w00 + c5.x * w10 + c6.x * w01 + c7.x * w11);
        float f1 = uz * (c0.y * w00 + c1.y * w10 + c2.y * w01 + c3.y * w11) +
                   wz * (c4.y * w00 + c5.y * w10 + c6.y * w01 + c7.y * w11);
        act[(2 * l + 0) * NT] = f0;
        act[(2 * l + 1) * NT] = f1;
    }

    // ---- hash-grid encode: hashed levels 5..15 (unrolled -> batched LDGs) ----
#pragma unroll
    for (int l = 5; l < 16; l++) {
        const unsigned res = RESV[l];
        const float fr = (float)res;
        float fx = px * fr, fy = py * fr, fz = pz * fr;
        float bx = floorf(fx), by = floorf(fy), bz = floorf(fz);
        float wx = fx - bx, wy = fy - by, wz = fz - bz;
        unsigned x0 = (unsigned)bx, y0 = (unsigned)by, z0 = (unsigned)bz;
        unsigned x1 = x0 + 1u;
        unsigned hy0 = y0 * 2654435761u, hy1 = hy0 + 2654435761u;
        unsigned hz0 = z0 * 805459861u, hz1 = hz0 + 805459861u;
        unsigned i0 = (x0 ^ hy0 ^ hz0) & TMASK;
        unsigned i1 = (x1 ^ hy0 ^ hz0) & TMASK;
        unsigned i2 = (x0 ^ hy1 ^ hz0) & TMASK;
        unsigned i3 = (x1 ^ hy1 ^ hz0) & TMASK;
        unsigned i4 = (x0 ^ hy0 ^ hz1) & TMASK;
        unsigned i5 = (x1 ^ hy0 ^ hz1) & TMASK;
        unsigned i6 = (x0 ^ hy1 ^ hz1) & TMASK;
        unsigned i7 = (x1 ^ hy1 ^ hz1) & TMASK;

        const float2* tb = (const float2*)table + (size_t)l * TSIZE;
        float2 c0 = __ldg(tb + i0), c1 = __ldg(tb + i1), c2 = __ldg(tb + i2), c3 = __ldg(tb + i3);
        float2 c4 = __ldg(tb + i4), c5 = __ldg(tb + i5), c6 = __ldg(tb + i6), c7 = __ldg(tb + i7);

        float ux = 1.0f - wx, uy = 1.0f - wy, uz = 1.0f - wz;
        float w00 = ux * uy, w10 = wx * uy, w01 = ux * wy, w11 = wx * wy;
        float f0 = uz * (c0.x * w00 + c1.x * w10 + c2.x * w01 + c3.x * w11) +
                   wz * (c4.x * w00 + c5.x * w10 + c6.x * w01 + c7.x * w11);
        float f1 = uz * (c0.y * w00 + c1.y * w10 + c2.y * w01 + c3.y * w11) +
                   wz * (c4.y * w00 + c5.y * w10 + c6.y * w01 + c7.y * w11);
        act[(2 * l + 0) * NT] = f0;
        act[(2 * l + 1) * NT] = f1;
    }

    unsigned long long acc[32];

    // ---- sigma MLP: 32 -> 64 (relu) -> 20(17) ----
    dense_c<32, 16, CW_WS1>(act, acc);
#pragma unroll
    for (int j = 0; j < 32; j++) {
        float lo, hi;
        unpack2(acc[j], lo, hi);
        act[(2 * j + 0) * NT] = fmaxf(lo, 0.0f);
        act[(2 * j + 1) * NT] = fmaxf(hi, 0.0f);
    }

    dense_c<64, 5, CW_WS2>(act, acc);
    float geo[20];
#pragma unroll
    for (int j = 0; j < 10; j++) unpack2(acc[j], geo[2 * j], geo[2 * j + 1]);
    float sigma_raw = geo[0];

    // ---- SH deg-4 direction encoding ----
    const float x = dx * 2.0f - 1.0f;
    const float y = dy * 2.0f - 1.0f;
    const float z = dz * 2.0f - 1.0f;
    float x2 = x * x, y2 = y * y, z2 = z * z;
    float xy = x * y, yz = y * z, xz = x * z;
    act[0 * NT] = 0.28209479177387814f;
    act[1 * NT] = -0.48860251190291987f * y;
    act[2 * NT] = 0.48860251190291987f * z;
    act[3 * NT] = -0.48860251190291987f * x;
    act[4 * NT] = 1.0925484305920792f * xy;
    act[5 * NT] = -1.0925484305920792f * yz;
    act[6 * NT] = 0.94617469575756f * z2 - 0.31539156525252f;
    act[7 * NT] = -1.0925484305920792f * xz;
    act[8 * NT] = 0.5462742152960396f * (x2 - y2);
    act[9 * NT] = 0.5900435899266435f * y * (-3.0f * x2 + y2);
    act[10 * NT] = 2.890611442640554f * xy * z;
    act[11 * NT] = 0.4570457994644657f * y * (1.0f - 5.0f * z2);
    act[12 * NT] = 0.3731763325901154f * z * (5.0f * z2 - 3.0f);
    act[13 * NT] = 0.4570457994644657f * x * (1.0f - 5.0f * z2);
    act[14 * NT] = 1.445305721320277f * z * (x2 - y2);
    act[15 * NT] = 0.5900435899266435f * x * (-x2 + 3.0f * y2);
#pragma unroll
    for (int j = 0; j < 16; j++) act[(16 + j) * NT] = geo[1 + j];

    // ---- rgb MLP: 32 -> 64 (relu) -> 64 (relu) -> 4(3) ----
    dense_c<32, 16, CW_WR1>(act, acc);
#pragma unroll
    for (int j = 0; j < 32; j++) {
        float lo, hi;
        unpack2(acc[j], lo, hi);
        act[(2 * j + 0) * NT] = fmaxf(lo, 0.0f);
        act[(2 * j + 1) * NT] = fmaxf(hi, 0.0f);
    }

    dense_c<64, 16, CW_WR2>(act, acc);
#pragma unroll
    for (int j = 0; j < 32; j++) {
        float lo, hi;
        unpack2(acc[j], lo, hi);
        act[(2 * j + 0) * NT] = fmaxf(lo, 0.0f);
        act[(2 * j + 1) * NT] = fmaxf(hi, 0.0f);
    }

    dense_c<64, 1, CW_WR3>(act, acc);
    float r0, r1, r2, r3;
    unpack2(acc[0], r0, r1);
    unpack2(acc[1], r2, r3);

    out[3 * gid + 0] = sigmoidf_(r0);
    out[3 * gid + 1] = sigmoidf_(r1);
    out[3 * gid + 2] = sigmoidf_(r2);
    out[(size_t)3 * N + gid] = fmaxf(sigma_raw, 0.0f);
}

extern "C" void kernel_launch(void* const* d_in, const int* in_sizes, int n_in,
                              void* d_out, int out_size) {
    const float* xyz = (const float*)d_in[0];
    const float* dir = (const float*)d_in[1];
    const float* table = (const float*)d_in[2];
    const float* ws1 = (const float*)d_in[3];
    const float* ws2 = (const float*)d_in[4];
    const float* wr1 = (const float*)d_in[5];
    const float* wr2 = (const float*)d_in[6];
    const float* wr3 = (const float*)d_in[7];
    float* out = (float*)d_out;
    int N = in_sizes[0] / 3;
    (void)n_in; (void)out_size;

    // stage weights: repack (pad) -> device buffer -> constant bank (D2D, capturable)
    repack_kernel<<<(CW_TOTAL + 255) / 256, 256>>>(ws1, ws2, wr1, wr2, wr3);
    void* packed_ptr = nullptr;
    cudaGetSymbolAddress(&packed_ptr, g_pack);
    cudaMemcpyToSymbolAsync(c_w, packed_ptr, CW_TOTAL * sizeof(float), 0,
                            cudaMemcpyDeviceToDevice, 0);

    cudaFuncSetAttribute(nerf_kernel, cudaFuncAttributeMaxDynamicSharedMemorySize, SMEM_BYTES);
    int grid = (N + NT - 1) / NT;
    nerf_kernel<<<grid, NT, SMEM_BYTES>>>(xyz, dir, table, out, N);
}